// round 14
// baseline (speedup 1.0000x reference)
#include <cuda_runtime.h>
#include <stdint.h>

// Problem constants (fixed by the reference setup)
#define Bn 16
#define Pn 784
#define Dn 10000
#define Ln 1000
#define Cn 10

#define WSTRIDE 384    // padded words per row: 3 granules of 128 words
#define NGR     3      // granules of 128 words (512B, uint4 per lane)
#define NCH     7      // 7 pixel chunks of 112 (8 warps x 14)
#define NGROUP  (Bn * NGR)           // 48 (b, granule) groups
#define NCTA    (NGROUP * NCH)       // 336 phase-A CTAs

// Scratch (allocation-free: device globals)
__device__ uint32_t g_vbits[Ln * WSTRIDE];     // sign bits of value_weight
__device__ uint32_t g_pbits[Pn * WSTRIDE];     // sign bits of position_weight
__device__ int      g_idxs[Bn * Pn];           // level idx PRE-SCALED by WSTRIDE
__device__ uint4    g_chunk[NCTA * 7 * 32];    // 7-plane x 4-comp chunk partials
__device__ float    g_partial[NGR * Bn * Cn];
__device__ int      g_gctr[NGROUP];            // per-group arrival counters
__device__ int      g_ctr2;                    // group completion counter

// ---------------------------------------------------------------------------
// Kernel 1: pre-scaled idx + sign-bit packing of both bipolar tables.
// Permuted bit layout: word w, bit l  <->  dim d = (w>>2)*128 + l*4 + (w&3).
// Words 0..319 from ballots; words 320..383 zero-padded.
// ---------------------------------------------------------------------------
__global__ void __launch_bounds__(256) pack_kernel(const float* __restrict__ x,
                                                   const float* __restrict__ posw,
                                                   const float* __restrict__ valw)
{
    const int tid     = blockIdx.x * blockDim.x + threadIdx.x;
    const int nthread = gridDim.x * blockDim.x;

    // level index: idx = clamp(rint(x*999), 0, 999), stored pre-scaled
    for (int i = tid; i < Bn * Pn; i += nthread) {
        int q = (int)rintf(x[i] * 999.0f);
        g_idxs[i] = min(max(q, 0), Ln - 1) * WSTRIDE;
    }

    // zero the pad words 320..383 of every row
    for (int i = tid; i < (Ln + Pn) * 16; i += nthread) {
        int row = i >> 4, qq = i & 15;
        uint32_t* base = (row < Ln) ? (g_vbits + row * WSTRIDE)
                                    : (g_pbits + (row - Ln) * WSTRIDE);
        *reinterpret_cast<uint4*>(base + 320 + qq * 4) = make_uint4(0u, 0u, 0u, 0u);
    }

    const int lane   = threadIdx.x & 31;
    const int warpId = tid >> 5;
    const int nWarps = nthread >> 5;
    const int totalTasks = (Ln + Pn) * 20;   // 20 x 512-dim tasks per row

    for (int task = warpId; task < totalTasks; task += nWarps) {
        int row = task / 20;
        int s   = task - row * 20;
        const float* src;
        uint32_t* dst;
        if (row < Ln) {
            src = valw + (size_t)row * Dn;
            dst = g_vbits + row * WSTRIDE;
        } else {
            src = posw + (size_t)(row - Ln) * Dn;
            dst = g_pbits + (row - Ln) * WSTRIDE;
        }

        uint32_t myword = 0;
        if (s < 19) {
            float4 v0 = *reinterpret_cast<const float4*>(src + s * 512 +   0 + lane * 4);
            float4 v1 = *reinterpret_cast<const float4*>(src + s * 512 + 128 + lane * 4);
            float4 v2 = *reinterpret_cast<const float4*>(src + s * 512 + 256 + lane * 4);
            float4 v3 = *reinterpret_cast<const float4*>(src + s * 512 + 384 + lane * 4);
#define PK(sub, vv)                                                          \
            {                                                                \
                uint32_t b0 = __ballot_sync(0xffffffffu, (vv).x < 0.0f);     \
                uint32_t b1 = __ballot_sync(0xffffffffu, (vv).y < 0.0f);     \
                uint32_t b2 = __ballot_sync(0xffffffffu, (vv).z < 0.0f);     \
                uint32_t b3 = __ballot_sync(0xffffffffu, (vv).w < 0.0f);     \
                if (lane == (sub)*4 + 0) myword = b0;                        \
                if (lane == (sub)*4 + 1) myword = b1;                        \
                if (lane == (sub)*4 + 2) myword = b2;                        \
                if (lane == (sub)*4 + 3) myword = b3;                        \
            }
            PK(0, v0) PK(1, v1) PK(2, v2) PK(3, v3)
#undef PK
        } else {
            // tail task (dims 9728..10239): per-lane validity
#pragma unroll
            for (int sub = 0; sub < 4; sub++) {
                int d0 = s * 512 + sub * 128 + lane * 4;
                bool valid = d0 < Dn;            // Dn % 4 == 0
                float4 v = make_float4(0.f, 0.f, 0.f, 0.f);
                if (valid) v = *reinterpret_cast<const float4*>(src + d0);
                uint32_t b0 = __ballot_sync(0xffffffffu, valid && v.x < 0.0f);
                uint32_t b1 = __ballot_sync(0xffffffffu, valid && v.y < 0.0f);
                uint32_t b2 = __ballot_sync(0xffffffffu, valid && v.z < 0.0f);
                uint32_t b3 = __ballot_sync(0xffffffffu, valid && v.w < 0.0f);
                if (lane == sub * 4 + 0) myword = b0;
                if (lane == sub * 4 + 1) myword = b1;
                if (lane == sub * 4 + 2) myword = b2;
                if (lane == sub * 4 + 3) myword = b3;
            }
        }
        if (lane < 16) dst[s * 16 + lane] = myword;      // coalesced 64B
    }
}

// ---------------------------------------------------------------------------
__device__ __forceinline__ void fadd(uint32_t a, uint32_t b, uint32_t cin,
                                     uint32_t& s, uint32_t& cout)
{
    uint32_t t = a ^ b;
    s    = t ^ cin;
    cout = (a & b) | (cin & t);
}

// add (s weight1, c weight2) into 4-plane counter (capacity 15)
__device__ __forceinline__ void merge2(uint32_t s, uint32_t c, uint32_t* cp)
{
    uint32_t carry = cp[0] & s;
    cp[0] ^= s;
    uint32_t x, co;
    fadd(cp[1], c, carry, x, co);
    cp[1] = x;
    uint32_t nc = cp[2] ^ co; co &= cp[2]; cp[2] = nc;
    cp[3] ^= co;
}

// 3:2 compress three 1-bit planes into 4-plane counter
__device__ __forceinline__ void csa3(uint32_t t0, uint32_t t1, uint32_t t2,
                                     uint32_t* cp)
{
    uint32_t u = t0 ^ t1;
    merge2(u ^ t2, (t0 & t1) | (t2 & u), cp);
}

// enc bit = 1 iff count < 392 (392 = 0b0110001000), 10 bit-planes
__device__ __forceinline__ uint32_t thr392(const uint32_t* c)
{
    uint32_t eq = ~0u, lt = 0u;
    eq &= ~c[9];
    lt |= eq & ~c[8]; eq &= c[8];
    lt |= eq & ~c[7]; eq &= c[7];
    eq &= ~c[6]; eq &= ~c[5]; eq &= ~c[4];
    lt |= eq & ~c[3];
    return lt;
}

// ---------------------------------------------------------------------------
// Kernel 2: CTA = (batch, 128-word granule, 112-px chunk), 256 threads =
// 8 warps x 14 px. Lane owns FOUR words (uint4, LDG.128); pbits offsets are
// compile-time immediates; vbits addresses need one IADD (pre-scaled idx).
// 3-px CSA into 4x4-plane counters; 3-round uint4 tree -> 7-plane chunk
// partial. 7th CTA of each (b,granule) group: sum -> threshold -> enc ->
// coalesced classify over the granule's contiguous 4096 dims. 48th group
// completion writes out. Deterministic; int atomics only.
// ---------------------------------------------------------------------------
__global__ void __launch_bounds__(256) hdc_main_kernel(const float* __restrict__ cw,
                                                       float* __restrict__ out)
{
    const int b    = blockIdx.x / (NGR * NCH);
    const int r0   = blockIdx.x - b * (NGR * NCH);
    const int g    = r0 / NCH;
    const int ch   = r0 - g * NCH;
    const int gid  = b * NGR + g;
    const int tid  = threadIdx.x;
    const int lane = tid & 31;
    const int wsub = tid >> 5;                   // 0..7

    __shared__ int      sIdx[112];
    __shared__ uint4    sBuf[4][7][32];
    __shared__ uint32_t sEnc[128];
    __shared__ int      sFlag[2];

    if (tid < 112) sIdx[tid] = g_idxs[b * Pn + ch * 112 + tid];
    __syncthreads();

    const int wb = g * 128 + lane * 4;           // lane's first word (16B aligned)
    const uint32_t* __restrict__ vbase = g_vbits + wb;
    const uint32_t* __restrict__ pbase = g_pbits + (ch * 112 + wsub * 14) * WSTRIDE + wb;
    const int lg0 = wsub * 14;

    uint32_t cnt[4][4];                          // [comp][plane], counts <= 14
#pragma unroll
    for (int c = 0; c < 4; c++)
#pragma unroll
        for (int j = 0; j < 4; j++) cnt[c][j] = 0u;

#pragma unroll
    for (int gx = 0; gx < 4; gx++) {             // 4 groups of 3 px
        const int k0 = gx * 3;
        int o0 = sIdx[lg0 + k0], o1 = sIdx[lg0 + k0 + 1], o2 = sIdx[lg0 + k0 + 2];
        uint4 q0 = __ldg(reinterpret_cast<const uint4*>(pbase + (k0 + 0) * WSTRIDE));
        uint4 q1 = __ldg(reinterpret_cast<const uint4*>(pbase + (k0 + 1) * WSTRIDE));
        uint4 q2 = __ldg(reinterpret_cast<const uint4*>(pbase + (k0 + 2) * WSTRIDE));
        uint4 v0 = __ldg(reinterpret_cast<const uint4*>(vbase + o0));
        uint4 v1 = __ldg(reinterpret_cast<const uint4*>(vbase + o1));
        uint4 v2 = __ldg(reinterpret_cast<const uint4*>(vbase + o2));
        csa3(v0.x ^ q0.x, v1.x ^ q1.x, v2.x ^ q2.x, cnt[0]);
        csa3(v0.y ^ q0.y, v1.y ^ q1.y, v2.y ^ q2.y, cnt[1]);
        csa3(v0.z ^ q0.z, v1.z ^ q1.z, v2.z ^ q2.z, cnt[2]);
        csa3(v0.w ^ q0.w, v1.w ^ q1.w, v2.w ^ q2.w, cnt[3]);
    }
    {   // final 2 px (half adder)
        int o0 = sIdx[lg0 + 12], o1 = sIdx[lg0 + 13];
        uint4 q0 = __ldg(reinterpret_cast<const uint4*>(pbase + 12 * WSTRIDE));
        uint4 q1 = __ldg(reinterpret_cast<const uint4*>(pbase + 13 * WSTRIDE));
        uint4 v0 = __ldg(reinterpret_cast<const uint4*>(vbase + o0));
        uint4 v1 = __ldg(reinterpret_cast<const uint4*>(vbase + o1));
        uint32_t t0, t1;
        t0 = v0.x ^ q0.x; t1 = v1.x ^ q1.x; merge2(t0 ^ t1, t0 & t1, cnt[0]);
        t0 = v0.y ^ q0.y; t1 = v1.y ^ q1.y; merge2(t0 ^ t1, t0 & t1, cnt[1]);
        t0 = v0.z ^ q0.z; t1 = v1.z ^ q1.z; merge2(t0 ^ t1, t0 & t1, cnt[2]);
        t0 = v0.w ^ q0.w; t1 = v1.w ^ q1.w; merge2(t0 ^ t1, t0 & t1, cnt[3]);
    }

    // ---- 3-round tree reduction across 8 warps: 4 -> 7 planes ----
    uint32_t a[4][7];
#pragma unroll
    for (int c = 0; c < 4; c++) {
#pragma unroll
        for (int j = 0; j < 4; j++) a[c][j] = cnt[c][j];
        a[c][4] = a[c][5] = a[c][6] = 0u;
    }

#pragma unroll
    for (int r = 0; r < 3; r++) {
        const int half = 4 >> r;                 // 4,2,1 readers
        const int np   = 4 + r;                  // planes valid in sources
        if (wsub >= half && wsub < 2 * half) {
#pragma unroll
            for (int j = 0; j < 7; j++)
                if (j < np)
                    sBuf[wsub - half][j][lane] =
                        make_uint4(a[0][j], a[1][j], a[2][j], a[3][j]);
        }
        __syncthreads();
        if (wsub < half) {
            uint32_t cx0 = 0u, cx1 = 0u, cx2 = 0u, cx3 = 0u;
#pragma unroll
            for (int j = 0; j < 7; j++) {
                if (j < np) {
                    uint4 v = sBuf[wsub][j][lane];
                    uint32_t s, co;
                    fadd(a[0][j], v.x, cx0, s, co); a[0][j] = s; cx0 = co;
                    fadd(a[1][j], v.y, cx1, s, co); a[1][j] = s; cx1 = co;
                    fadd(a[2][j], v.z, cx2, s, co); a[2][j] = s; cx2 = co;
                    fadd(a[3][j], v.w, cx3, s, co); a[3][j] = s; cx3 = co;
                } else if (j == np) {
                    a[0][j] = cx0; a[1][j] = cx1; a[2][j] = cx2; a[3][j] = cx3;
                }
            }
        }
        __syncthreads();
    }

    if (wsub == 0) {                             // write 7-plane chunk partial
#pragma unroll
        for (int j = 0; j < 7; j++)
            g_chunk[((gid * NCH + ch) * 7 + j) * 32 + lane] =
                make_uint4(a[0][j], a[1][j], a[2][j], a[3][j]);
    }
    __syncthreads();

    // ---- group arrival: 7th CTA of this (b,granule) runs phase B ----
    if (tid == 0) {
        __threadfence();
        int prev = atomicAdd(&g_gctr[gid], 1);
        sFlag[0] = (prev == NCH - 1);
        if (sFlag[0]) g_gctr[gid] = 0;           // reset for next replay
    }
    __syncthreads();
    if (!sFlag[0]) return;

    __threadfence();                             // acquire peer chunk partials

    // ---- phase B: warp 0 sums 7 chunks -> 10 planes -> enc ----
    if (wsub == 0) {
        uint32_t s[4][10];
#pragma unroll
        for (int c = 0; c < 4; c++)
#pragma unroll
            for (int j = 0; j < 10; j++) s[c][j] = 0u;
#pragma unroll
        for (int c2 = 0; c2 < NCH; c2++) {
            uint32_t cx0 = 0u, cx1 = 0u, cx2 = 0u, cx3 = 0u;
#pragma unroll
            for (int j = 0; j < 7; j++) {
                uint4 v = __ldg(&g_chunk[((gid * NCH + c2) * 7 + j) * 32 + lane]);
                uint32_t ss, co;
                fadd(s[0][j], v.x, cx0, ss, co); s[0][j] = ss; cx0 = co;
                fadd(s[1][j], v.y, cx1, ss, co); s[1][j] = ss; cx1 = co;
                fadd(s[2][j], v.z, cx2, ss, co); s[2][j] = ss; cx2 = co;
                fadd(s[3][j], v.w, cx3, ss, co); s[3][j] = ss; cx3 = co;
            }
#pragma unroll
            for (int j = 7; j < 10; j++) {
                uint32_t nc;
                nc = s[0][j] ^ cx0; cx0 &= s[0][j]; s[0][j] = nc;
                nc = s[1][j] ^ cx1; cx1 &= s[1][j]; s[1][j] = nc;
                nc = s[2][j] ^ cx2; cx2 &= s[2][j]; s[2][j] = nc;
                nc = s[3][j] ^ cx3; cx3 &= s[3][j]; s[3][j] = nc;
            }
        }
        sEnc[lane * 4 + 0] = thr392(s[0]);
        sEnc[lane * 4 + 1] = thr392(s[1]);
        sEnc[lane * 4 + 2] = thr392(s[2]);
        sEnc[lane * 4 + 3] = thr392(s[3]);
    }
    __syncthreads();

    // ---- coalesced classify over this granule's dims [g*4096, g*4096+4096).
    // float4 at d0 = g*4096 + i*128 + lane*4 maps to bit lane of local words
    // i*4+{0..3}; enc words are warp-uniform smem reads.
    for (int c = wsub; c < Cn; c += 8) {
        const float* __restrict__ wrow = cw + c * Dn + g * 4096;
        float acc = 0.0f;
#pragma unroll 8
        for (int i = 0; i < 32; i++) {
            int d0 = g * 4096 + i * 128 + lane * 4;
            if (d0 < Dn) {                       // Dn%4==0 -> whole float4 valid
                uint32_t w0 = sEnc[i * 4 + 0];
                uint32_t w1 = sEnc[i * 4 + 1];
                uint32_t w2 = sEnc[i * 4 + 2];
                uint32_t w3 = sEnc[i * 4 + 3];
                float4 v = *reinterpret_cast<const float4*>(wrow + i * 128 + lane * 4);
                acc += ((w0 >> lane) & 1u) ? v.x : -v.x;
                acc += ((w1 >> lane) & 1u) ? v.y : -v.y;
                acc += ((w2 >> lane) & 1u) ? v.z : -v.z;
                acc += ((w3 >> lane) & 1u) ? v.w : -v.w;
            }
        }
        // deterministic fixed-order warp reduction
#pragma unroll
        for (int off = 16; off >= 1; off >>= 1)
            acc += __shfl_xor_sync(0xffffffffu, acc, off);
        if (lane == 0) g_partial[(g * Bn + b) * Cn + c] = acc;
    }

    // ---- 48th group completion writes the final output ----
    __syncthreads();
    if (tid == 0) {
        __threadfence();
        int prev = atomicAdd(&g_ctr2, 1);
        sFlag[1] = (prev == NGROUP - 1);
    }
    __syncthreads();
    if (sFlag[1]) {
        __threadfence();
        if (tid < Bn * Cn) {
            float s = 0.0f;
#pragma unroll
            for (int gg = 0; gg < NGR; gg++) s += g_partial[gg * Bn * Cn + tid];
            out[tid] = s;
        }
        if (tid == 0) g_ctr2 = 0;                // reset for next replay
    }
}

// ---------------------------------------------------------------------------
extern "C" void kernel_launch(void* const* d_in, const int* in_sizes, int n_in,
                              void* d_out, int out_size)
{
    const float* x    = (const float*)d_in[0];   // [16,28,28]
    const float* posw = (const float*)d_in[1];   // [784,10000]
    const float* valw = (const float*)d_in[2];   // [1000,10000]
    const float* cw   = (const float*)d_in[3];   // [10,10000]
    float* out = (float*)d_out;                  // [16,10]

    pack_kernel<<<1184, 256>>>(x, posw, valw);
    hdc_main_kernel<<<NCTA, 256>>>(cw, out);
}